// round 9
// baseline (speedup 1.0000x reference)
#include <cuda_runtime.h>
#include <cstdint>

#define BATCH    2048
#define NCLS     50257
#define KPOS     20
#define THREADS  256
#define QPR      4                    // quarters per row
#define QF4      3141                 // float4 per quarter (4*3141 >= max n4 12564)
#define GRID     (BATCH * QPR)        // 8192 CTAs
#define STAGE_F4 512                  // float4 per pipeline stage (8 KB)

// Scratch (device globals => allocation-free)
__device__ float g_q[GRID];           // per-quarter partial sums (log2 domain)
__device__ float g_a[BATCH];          // per-row: pos/K - w*corr
__device__ float g_w[BATCH];          // per-row: 1/(NCLS - uniq)
__device__ int   g_ticket;

__device__ __forceinline__ float ex2f(float x) {
    float r; asm("ex2.approx.ftz.f32 %0, %1;" : "=f"(r) : "f"(x)); return r;
}
__device__ __forceinline__ float lg2f(float x) {
    float r; asm("lg2.approx.ftz.f32 %0, %1;" : "=f"(r) : "f"(x)); return r;
}

#define L2E 1.4426950408889634f
#define LN2 0.6931471805599453f

__device__ __forceinline__ float log_sig(float z) {
    return -LN2 * lg2f(1.0f + ex2f(-z * L2E));
}
// product of (1 + 2^(x_i * log2e)) over a float4
__device__ __forceinline__ float prod4(float4 v) {
    float t0 = ex2f(v.x * L2E);
    float t1 = ex2f(v.y * L2E);
    float t2 = ex2f(v.z * L2E);
    float t3 = ex2f(v.w * L2E);
    return ((1.0f + t0) * (1.0f + t1)) * ((1.0f + t2) * (1.0f + t3));
}

__device__ __forceinline__ uint32_t smem_u32(const void* p) {
    uint32_t a;
    asm("{ .reg .u64 t; cvta.to.shared.u64 t, %1; cvt.u32.u64 %0, t; }"
        : "=r"(a) : "l"(p));
    return a;
}
__device__ __forceinline__ void mbar_init(uint32_t a, uint32_t cnt) {
    asm volatile("mbarrier.init.shared.b64 [%0], %1;" :: "r"(a), "r"(cnt) : "memory");
}
__device__ __forceinline__ void mbar_expect_tx(uint32_t a, uint32_t bytes) {
    asm volatile("mbarrier.arrive.expect_tx.shared.b64 _, [%0], %1;"
                 :: "r"(a), "r"(bytes) : "memory");
}
__device__ __forceinline__ void bulk_g2s(uint32_t dst, const void* src,
                                         uint32_t bytes, uint32_t mbar) {
    asm volatile(
        "cp.async.bulk.shared::cta.global.mbarrier::complete_tx::bytes "
        "[%0], [%1], %2, [%3];"
        :: "r"(dst), "l"(src), "r"(bytes), "r"(mbar) : "memory");
}
__device__ __forceinline__ void mbar_wait(uint32_t a, uint32_t ph) {
    asm volatile(
        "{\n\t.reg .pred P;\n"
        "WL_%=:\n\t"
        "mbarrier.try_wait.parity.acquire.cta.shared::cta.b64 P, [%0], %1, 0x989680;\n\t"
        "@P bra WD_%=;\n\t"
        "bra WL_%=;\n"
        "WD_%=:\n\t}"
        :: "r"(a), "r"(ph) : "memory");
}

__global__ __launch_bounds__(THREADS, 8) void mlsml_kernel(
    const float* __restrict__ x,    // [BATCH, NCLS]
    const int*   __restrict__ tgt,  // [BATCH, KPOS]
    float*       __restrict__ out)  // [1]
{
    __shared__ alignas(16) float4 buf[2][STAGE_F4];   // 2 x 8 KB
    __shared__ uint64_t mbars[2];
    __shared__ float red[THREADS / 32];
    __shared__ int   sIsLast;

    const int bid = blockIdx.x;
    const int row = bid >> 2;
    const int q   = bid & 3;
    const int tid = threadIdx.x;
    const float* __restrict__ xr = x + (size_t)row * NCLS;

    // Row base offset mod 4 == row mod 4 (50257 % 4 == 1) -> peel to 16B align.
    const int head = (4 - (row & 3)) & 3;
    const int n4   = (NCLS - head) >> 2;
    const int rem  = (NCLS - head) & 3;

    const int lo   = q * QF4;
    const int hi   = min(n4, lo + QF4);
    const int nf4  = hi - lo;
    const int nst  = (nf4 + STAGE_F4 - 1) / STAGE_F4;
    const float4* __restrict__ src = (const float4*)(xr + head) + lo;

    const uint32_t mb0  = smem_u32(&mbars[0]);
    const uint32_t mb1  = smem_u32(&mbars[1]);
    const uint32_t sbuf = smem_u32(&buf[0][0]);

    // Init barriers, fence async proxy, prime the 2-stage pipeline.
    if (tid == 0) { mbar_init(mb0, 1); mbar_init(mb1, 1); }
    __syncthreads();
    asm volatile("fence.proxy.async.shared::cta;" ::: "memory");
    if (tid == 0) {
        #pragma unroll
        for (int s = 0; s < 2; s++) {
            if (s < nst) {
                uint32_t bytes = (uint32_t)min(STAGE_F4, nf4 - s * STAGE_F4) * 16u;
                uint32_t mb = s ? mb1 : mb0;
                mbar_expect_tx(mb, bytes);
                bulk_g2s(sbuf + (uint32_t)s * (STAGE_F4 * 16), src + s * STAGE_F4,
                         bytes, mb);
            }
        }
    }

    // Edge elements (head/tail of row) via direct global loads.
    float s2 = 0.0f;
    if (q == 0 && tid < head)
        s2 += lg2f(1.0f + ex2f(xr[tid] * L2E));
    if (q == QPR - 1 && tid < rem)
        s2 += lg2f(1.0f + ex2f(xr[head + 4 * n4 + tid] * L2E));

    // Pipelined main loop: consume stage k from buf[k&1], prefetch stage k+2.
    for (int k = 0; k < nst; k++) {
        const int      b   = k & 1;
        const uint32_t mb  = b ? mb1 : mb0;
        const int      ph  = (k >> 1) & 1;
        mbar_wait(mb, ph);

        const int sf4 = min(STAGE_F4, nf4 - k * STAGE_F4);
        if (sf4 == STAGE_F4) {
            float4 a = buf[b][tid];
            float4 c = buf[b][tid + THREADS];
            s2 += lg2f(prod4(a) * prod4(c));
        } else {
            if (tid < sf4)           s2 += lg2f(prod4(buf[b][tid]));
            if (tid + THREADS < sf4) s2 += lg2f(prod4(buf[b][tid + THREADS]));
        }
        __syncthreads();   // all consumers done with buf[b] before refill

        if (tid == 0 && k + 2 < nst) {
            uint32_t bytes = (uint32_t)min(STAGE_F4, nf4 - (k + 2) * STAGE_F4) * 16u;
            mbar_expect_tx(mb, bytes);
            bulk_g2s(sbuf + (uint32_t)b * (STAGE_F4 * 16), src + (k + 2) * STAGE_F4,
                     bytes, mb);
        }
    }

    // Block reduction of s2
    #pragma unroll
    for (int o = 16; o > 0; o >>= 1)
        s2 += __shfl_down_sync(0xffffffffu, s2, o);
    const int lane = tid & 31, wid = tid >> 5;
    if (lane == 0) red[wid] = s2;
    __syncthreads();

    if (wid == 0) {
        float S2 = (lane < THREADS / 32) ? red[lane] : 0.0f;
        #pragma unroll
        for (int o = 4; o > 0; o >>= 1)
            S2 += __shfl_down_sync(0xffffffffu, S2, o);
        if (lane == 0) g_q[bid] = S2;

        // Quarter 0 also computes the row target epilogue (warp-parallel K=20)
        if (q == 0) {
            float pos = 0.0f, corr = 0.0f;
            int   uq  = 0;
            if (lane < KPOS) {
                int   idx = __ldg(tgt + row * KPOS + lane);
                float v   = __ldg(xr + idx);
                pos = log_sig(v);
                unsigned m = __match_any_sync(0x000FFFFFu, idx);
                if ((m & (unsigned)(-(int)m)) == (1u << lane)) {
                    corr = log_sig(-v);
                    uq   = 1;
                }
            }
            #pragma unroll
            for (int o = 16; o > 0; o >>= 1) {
                pos  += __shfl_down_sync(0xffffffffu, pos,  o);
                corr += __shfl_down_sync(0xffffffffu, corr, o);
                uq   += __shfl_down_sync(0xffffffffu, uq,   o);
            }
            if (lane == 0) {
                float w = 1.0f / (float)(NCLS - uq);
                g_w[row] = w;
                g_a[row] = pos * (1.0f / KPOS) - corr * w;
            }
        }

        if (lane == 0) {
            __threadfence();
            int ticket = atomicAdd(&g_ticket, 1);
            sIsLast = (ticket == GRID - 1);
        }
    }
    __syncthreads();

    // Last CTA: deterministic fixed-order per-row reassembly + final mean
    if (sIsLast) {
        __threadfence();
        float acc = 0.0f;
        for (int r = tid; r < BATCH; r += THREADS) {
            float ss = (__ldcg(&g_q[4 * r + 0]) + __ldcg(&g_q[4 * r + 1])) +
                       (__ldcg(&g_q[4 * r + 2]) + __ldcg(&g_q[4 * r + 3]));
            float S = -LN2 * ss;   // sum log_sigmoid(-x) over row r
            acc += __ldcg(&g_a[r]) + __ldcg(&g_w[r]) * S;
        }
        #pragma unroll
        for (int o = 16; o > 0; o >>= 1)
            acc += __shfl_down_sync(0xffffffffu, acc, o);
        if (lane == 0) red[wid] = acc;
        __syncthreads();
        if (tid == 0) {
            float S = 0.0f;
            #pragma unroll
            for (int w = 0; w < THREADS / 32; w++) S += red[w];
            out[0] = -S / (float)BATCH;
            g_ticket = 0;  // reset for next graph replay
        }
    }
}

extern "C" void kernel_launch(void* const* d_in, const int* in_sizes, int n_in,
                              void* d_out, int out_size) {
    const float* x   = (const float*)d_in[0];
    const int*   tgt = (const int*)d_in[1];
    float*       out = (float*)d_out;
    mlsml_kernel<<<GRID, THREADS>>>(x, tgt, out);
}